// round 12
// baseline (speedup 1.0000x reference)
#include <cuda_runtime.h>
#include <cstddef>

// HaarDown: x (B=8, C=64, H=512, W=512) f32 -> out (B, C*3, H2=256, W2=256) f32
// 2x2 block [a b; c d]:
//   o0 = (a - b - c + d) * 0.5
//   o1 = (a - b + c - d) * 0.5
//   o2 = (a + b - c - d) * 0.5
// out channel = c*3 + k
//
// CONVERGED CHAMPION (8x repeat-stable, 137.25-137.31 us):
// streaming kernel pinned at the B300 DRAM/LTS fabric ceiling — ~6.86 TB/s
// (86% of 8 TB/s spec = achievable mixed 4:3 read/write limit), moving
// exactly the minimal 888 MB (bandwidth x time audit). Demand-insensitive
// across occ 37-90%, MLP 4-8, 128/256-bit ops, flat/persistent grids,
// block sizes, store policies — the binding resource is the memory fabric,
// not the SMs. 256-bit vector ld/st, flat grid, 512-thread blocks,
// evict-first stores.

namespace {
constexpr int B  = 8;
constexpr int C  = 64;
constexpr int H  = 512;
constexpr int W  = 512;
constexpr int H2 = H / 2;   // 256
constexpr int W2 = W / 2;   // 256
constexpr int WG = W2 / 8;  // 32 groups of 8 output columns per row
constexpr int THREADS_PER_BLOCK = 512;
constexpr long long TOTAL_THREADS = (long long)B * C * H2 * WG; // 4,194,304
constexpr int NUM_BLOCKS = (int)(TOTAL_THREADS / THREADS_PER_BLOCK); // 8192
}

__device__ __forceinline__ void ldg256_nc(const float* p, float v[8]) {
    asm volatile(
        "ld.global.nc.v8.f32 {%0,%1,%2,%3,%4,%5,%6,%7}, [%8];"
        : "=f"(v[0]), "=f"(v[1]), "=f"(v[2]), "=f"(v[3]),
          "=f"(v[4]), "=f"(v[5]), "=f"(v[6]), "=f"(v[7])
        : "l"(p));
}

__device__ __forceinline__ void stg256_cs(float* p, const float v[8]) {
    asm volatile(
        "st.global.cs.v8.f32 [%0], {%1,%2,%3,%4,%5,%6,%7,%8};"
        :: "l"(p),
           "f"(v[0]), "f"(v[1]), "f"(v[2]), "f"(v[3]),
           "f"(v[4]), "f"(v[5]), "f"(v[6]), "f"(v[7])
        : "memory");
}

__global__ __launch_bounds__(THREADS_PER_BLOCK)
void haar_down_kernel(const float* __restrict__ x, float* __restrict__ out) {
    int tid = blockIdx.x * THREADS_PER_BLOCK + threadIdx.x;

    int wg = tid & (WG - 1);           // group of 8 output columns
    int h2 = (tid >> 5) & (H2 - 1);    // output row
    int bc = tid >> 13;                // fused (b, c): 0..511

    // Input: two rows of 16 consecutive floats (covers 8 output columns).
    // Front-batch all 4 independent 256-bit loads (128B in flight).
    const float* p0 = x + (size_t)bc * (H * W) + (size_t)(2 * h2) * W + wg * 16;
    float r0[16], r1[16];
    ldg256_nc(p0,          r0);
    ldg256_nc(p0 + 8,      r0 + 8);
    ldg256_nc(p0 + W,      r1);
    ldg256_nc(p0 + W + 8,  r1 + 8);

    float o0[8], o1[8], o2[8];
    #pragma unroll
    for (int j = 0; j < 8; j++) {
        float a = r0[2 * j], b = r0[2 * j + 1];
        float c = r1[2 * j], d = r1[2 * j + 1];
        float amb = a - b;
        float apb = a + b;
        float cmd = c - d;
        float cpd = c + d;
        o0[j] = (amb - cmd) * 0.5f;   // a-b-c+d
        o1[j] = (amb + cmd) * 0.5f;   // a-b+c-d
        o2[j] = (apb - cpd) * 0.5f;   // a+b-c-d
    }

    // Output: channel = c*3 + k, bc = b*C + c
    int b = bc >> 6;          // / 64
    int c = bc & 63;          // % 64
    constexpr int PLANE = H2 * W2; // 65536
    float* obase = out + ((size_t)(b * (C * 3) + c * 3) * PLANE)
                       + (size_t)h2 * W2 + wg * 8;

    stg256_cs(obase,             o0);
    stg256_cs(obase + PLANE,     o1);
    stg256_cs(obase + 2 * PLANE, o2);
}

extern "C" void kernel_launch(void* const* d_in, const int* in_sizes, int n_in,
                              void* d_out, int out_size) {
    const float* x = (const float*)d_in[0];
    float* out = (float*)d_out;
    haar_down_kernel<<<NUM_BLOCKS, THREADS_PER_BLOCK>>>(x, out);
}

// round 13
// speedup vs baseline: 1.0007x; 1.0007x over previous
#include <cuda_runtime.h>
#include <cstddef>

// HaarDown: x (B=8, C=64, H=512, W=512) f32 -> out (B, C*3, H2=256, W2=256) f32
// 2x2 block [a b; c d]:
//   o0 = (a - b - c + d) * 0.5
//   o1 = (a - b + c - d) * 0.5
//   o2 = (a + b - c - d) * 0.5
// out channel = c*3 + k
//
// CONVERGED CHAMPION (9x repeat-stable, 137.25-137.31 us):
// streaming kernel pinned at the B300 DRAM/LTS fabric ceiling — ~6.86 TB/s
// (86% of 8 TB/s spec = achievable mixed 4:3 read/write limit), moving
// exactly the minimal 888 MB (bandwidth x time audit). Demand-insensitive
// across occ 37-90%, MLP 4-8, 128/256-bit ops, flat/persistent grids,
// block sizes, store policies — the binding resource is the memory fabric,
// not the SMs. 256-bit vector ld/st, flat grid, 512-thread blocks,
// evict-first stores.

namespace {
constexpr int B  = 8;
constexpr int C  = 64;
constexpr int H  = 512;
constexpr int W  = 512;
constexpr int H2 = H / 2;   // 256
constexpr int W2 = W / 2;   // 256
constexpr int WG = W2 / 8;  // 32 groups of 8 output columns per row
constexpr int THREADS_PER_BLOCK = 512;
constexpr long long TOTAL_THREADS = (long long)B * C * H2 * WG; // 4,194,304
constexpr int NUM_BLOCKS = (int)(TOTAL_THREADS / THREADS_PER_BLOCK); // 8192
}

__device__ __forceinline__ void ldg256_nc(const float* p, float v[8]) {
    asm volatile(
        "ld.global.nc.v8.f32 {%0,%1,%2,%3,%4,%5,%6,%7}, [%8];"
        : "=f"(v[0]), "=f"(v[1]), "=f"(v[2]), "=f"(v[3]),
          "=f"(v[4]), "=f"(v[5]), "=f"(v[6]), "=f"(v[7])
        : "l"(p));
}

__device__ __forceinline__ void stg256_cs(float* p, const float v[8]) {
    asm volatile(
        "st.global.cs.v8.f32 [%0], {%1,%2,%3,%4,%5,%6,%7,%8};"
        :: "l"(p),
           "f"(v[0]), "f"(v[1]), "f"(v[2]), "f"(v[3]),
           "f"(v[4]), "f"(v[5]), "f"(v[6]), "f"(v[7])
        : "memory");
}

__global__ __launch_bounds__(THREADS_PER_BLOCK)
void haar_down_kernel(const float* __restrict__ x, float* __restrict__ out) {
    int tid = blockIdx.x * THREADS_PER_BLOCK + threadIdx.x;

    int wg = tid & (WG - 1);           // group of 8 output columns
    int h2 = (tid >> 5) & (H2 - 1);    // output row
    int bc = tid >> 13;                // fused (b, c): 0..511

    // Input: two rows of 16 consecutive floats (covers 8 output columns).
    // Front-batch all 4 independent 256-bit loads (128B in flight).
    const float* p0 = x + (size_t)bc * (H * W) + (size_t)(2 * h2) * W + wg * 16;
    float r0[16], r1[16];
    ldg256_nc(p0,          r0);
    ldg256_nc(p0 + 8,      r0 + 8);
    ldg256_nc(p0 + W,      r1);
    ldg256_nc(p0 + W + 8,  r1 + 8);

    float o0[8], o1[8], o2[8];
    #pragma unroll
    for (int j = 0; j < 8; j++) {
        float a = r0[2 * j], b = r0[2 * j + 1];
        float c = r1[2 * j], d = r1[2 * j + 1];
        float amb = a - b;
        float apb = a + b;
        float cmd = c - d;
        float cpd = c + d;
        o0[j] = (amb - cmd) * 0.5f;   // a-b-c+d
        o1[j] = (amb + cmd) * 0.5f;   // a-b+c-d
        o2[j] = (apb - cpd) * 0.5f;   // a+b-c-d
    }

    // Output: channel = c*3 + k, bc = b*C + c
    int b = bc >> 6;          // / 64
    int c = bc & 63;          // % 64
    constexpr int PLANE = H2 * W2; // 65536
    float* obase = out + ((size_t)(b * (C * 3) + c * 3) * PLANE)
                       + (size_t)h2 * W2 + wg * 8;

    stg256_cs(obase,             o0);
    stg256_cs(obase + PLANE,     o1);
    stg256_cs(obase + 2 * PLANE, o2);
}

extern "C" void kernel_launch(void* const* d_in, const int* in_sizes, int n_in,
                              void* d_out, int out_size) {
    const float* x = (const float*)d_in[0];
    float* out = (float*)d_out;
    haar_down_kernel<<<NUM_BLOCKS, THREADS_PER_BLOCK>>>(x, out);
}